// round 4
// baseline (speedup 1.0000x reference)
#include <cuda_runtime.h>
#include <math.h>
#include <stdint.h>

#define BB 128
#define TT 512
#define DD 1024
#define HH 1024
#define NGATE 4096   // 4*H
#define NCTA 128     // persistent grid size (all co-resident)

// Scratch (static device globals — no runtime allocation).
__device__ float g_xg[(size_t)TT * BB * NGATE];        // [t][b][4H] input projections
__device__ float g_part[4 * BB * NGATE];               // split-K partials [ks][b][4H]
__device__ float g_h[BB * HH];                         // recurrent h
__device__ unsigned g_bar;                             // grid barrier counter (never reset)

__device__ __forceinline__ uint32_t f2tf32(float f)
{
    uint32_t u;
    asm("cvt.rna.tf32.f32 %0, %1;" : "=r"(u) : "f"(f));
    return u;
}

__device__ __forceinline__ void mma_tf32(float* d, const uint32_t* a, const uint32_t* b)
{
    asm volatile(
        "mma.sync.aligned.m16n8k8.row.col.f32.tf32.tf32.f32 "
        "{%0,%1,%2,%3},{%4,%5,%6,%7},{%8,%9},{%0,%1,%2,%3};"
        : "+f"(d[0]), "+f"(d[1]), "+f"(d[2]), "+f"(d[3])
        : "r"(a[0]), "r"(a[1]), "r"(a[2]), "r"(a[3]), "r"(b[0]), "r"(b[1]));
}

// k-permutation within each 8-group: pos = (k&~7) | ((k&3)<<1) | ((k>>2)&1)
// -> (cq, cq+4) pairs are adjacent, fetched with one LDS.64.

// ---------------------------------------------------------------------------
// GEMM1 (tf32): xg[t][b][n] = sum_k x[b][t][k] * Wx[g][k][h]
// Block tile 128m x 128n x 32k, 8 warps 2x4, warp tile 64x32 (4x4 m16n8k8).
// Smem layouts: As[m][kperm(32)+2pad], Bs[n][kperm(32)+2pad].
// ---------------------------------------------------------------------------
__global__ __launch_bounds__(256, 2) void gemm_xgates(
    const float* __restrict__ x, const float* __restrict__ Wx,
    float* __restrict__ out)
{
    __shared__ uint32_t As[128 * 34];
    __shared__ uint32_t Bs[128 * 34];

    const int tid  = threadIdx.x;
    const int lane = tid & 31;
    const int wid  = tid >> 5;
    const int gq   = lane >> 2;   // 0..7
    const int cq   = lane & 3;    // 0..3

    const int t  = blockIdx.y;
    const int n0 = blockIdx.x * 128;
    const int gg = n0 >> 10;
    const int hb = n0 & 1023;

    const int m0w = (wid >> 2) * 64;
    const int n0w = (wid & 3) * 32;

    float acc[4][4][4];
#pragma unroll
    for (int i = 0; i < 4; i++)
#pragma unroll
        for (int j = 0; j < 4; j++)
#pragma unroll
            for (int e = 0; e < 4; e++) acc[i][j][e] = 0.f;

    const float* Wg = Wx + (size_t)gg * DD * HH + hb;

    // A writer: m = tid>>1, k-half (tid&1)*16, 4 float4
    const int am  = tid >> 1;
    const int akq = (tid & 1) * 16;
    // B writer: k = lane, n chunk wid*16, 4 float4 along n
    const int bk  = lane;
    const int bn0 = wid * 16;
    const int bkp = (bk & ~7) | ((bk & 3) << 1) | ((bk >> 2) & 1);

    for (int kt = 0; kt < DD; kt += 32) {
        // A tile
        {
            const float* src = x + (size_t)am * (TT * DD) + (size_t)t * DD + kt + akq;
#pragma unroll
            for (int j = 0; j < 4; j++) {
                float4 v = *(const float4*)(src + j * 4);
                int k0 = akq + j * 4;
                int cb = (k0 & ~7) | ((k0 >> 2) & 1);
                uint32_t* d = &As[am * 34 + cb];
                d[0] = f2tf32(v.x); d[2] = f2tf32(v.y);
                d[4] = f2tf32(v.z); d[6] = f2tf32(v.w);
            }
        }
        // B tile
        {
            const float* src = Wg + (size_t)(kt + bk) * HH + bn0;
#pragma unroll
            for (int j = 0; j < 4; j++) {
                float4 v = *(const float4*)(src + j * 4);
                int nr = bn0 + j * 4;
                Bs[(nr + 0) * 34 + bkp] = f2tf32(v.x);
                Bs[(nr + 1) * 34 + bkp] = f2tf32(v.y);
                Bs[(nr + 2) * 34 + bkp] = f2tf32(v.z);
                Bs[(nr + 3) * 34 + bkp] = f2tf32(v.w);
            }
        }
        __syncthreads();

#pragma unroll
        for (int kk = 0; kk < 4; kk++) {
            const int kc = kk * 8 + 2 * cq;
            uint32_t af[4][4], bf[4][2];
#pragma unroll
            for (int mt = 0; mt < 4; mt++) {
                int m = m0w + mt * 16 + gq;
                uint2 va = *(const uint2*)&As[m * 34 + kc];
                uint2 vb = *(const uint2*)&As[(m + 8) * 34 + kc];
                af[mt][0] = va.x; af[mt][1] = vb.x;
                af[mt][2] = va.y; af[mt][3] = vb.y;
            }
#pragma unroll
            for (int nt = 0; nt < 4; nt++) {
                uint2 w = *(const uint2*)&Bs[(n0w + nt * 8 + gq) * 34 + kc];
                bf[nt][0] = w.x; bf[nt][1] = w.y;
            }
#pragma unroll
            for (int mt = 0; mt < 4; mt++)
#pragma unroll
                for (int nt = 0; nt < 4; nt++)
                    mma_tf32(acc[mt][nt], af[mt], bf[nt]);
        }
        __syncthreads();
    }

#pragma unroll
    for (int mt = 0; mt < 4; mt++) {
        int r0 = m0w + mt * 16 + gq;
#pragma unroll
        for (int nt = 0; nt < 4; nt++) {
            int cc = n0 + n0w + nt * 8 + 2 * cq;
            float* p0 = out + ((size_t)t * BB + r0) * NGATE + cc;
            float* p1 = out + ((size_t)t * BB + r0 + 8) * NGATE + cc;
            *(float2*)p0 = make_float2(acc[mt][nt][0], acc[mt][nt][1]);
            *(float2*)p1 = make_float2(acc[mt][nt][2], acc[mt][nt][3]);
        }
    }
}

// ---------------------------------------------------------------------------
// Grid barrier: generation counter; poll with volatile load (no atomic RMW).
// ---------------------------------------------------------------------------
__device__ __forceinline__ void grid_barrier()
{
    __syncthreads();
    if (threadIdx.x == 0) {
        __threadfence();
        unsigned old = atomicAdd(&g_bar, 1u);
        unsigned target = (old / NCTA + 1u) * (unsigned)NCTA;
        while (*(volatile unsigned*)&g_bar < target) { __nanosleep(32); }
        __threadfence();
    }
    __syncthreads();
}

// ---------------------------------------------------------------------------
// Persistent recurrence (tf32): 128 CTAs x 256 threads, 512 steps.
// CTA = (n-tile 0..31, k-split 0..3). Wh slice (256k x 128n) persists in smem
// as BsW[n][kperm(256)+8pad]; h streams per step in 4 chunks of k64 through
// ping-pong AsH[2][m][kperm(64)+2pad] with register-staged LDG prefetch.
// One __syncthreads per chunk. Activation: CTA b owns row b, c in registers.
// ---------------------------------------------------------------------------
extern __shared__ uint32_t dynsmem[];

__global__ __launch_bounds__(256) void lstm_recurrence(
    const float* __restrict__ Wh, const float* __restrict__ xg,
    const float* __restrict__ bias, float* __restrict__ out)
{
    uint32_t* BsW = dynsmem;                       // 128 * 264
    uint32_t* AsH = dynsmem + 128 * 264;           // 2 * 128 * 66

    const int tid  = threadIdx.x;
    const int lane = tid & 31;
    const int wid  = tid >> 5;
    const int gq   = lane >> 2;
    const int cq   = lane & 3;

    const int nt = blockIdx.x & 31;
    const int ks = blockIdx.x >> 5;
    const int n0 = nt * 128;
    const int gg = n0 >> 10;
    const int hb = n0 & 1023;
    const int k0 = ks * 256;

    const int m0w = (wid >> 2) * 64;
    const int n0w = (wid & 3) * 32;

    const float* Wg = Wh + (size_t)gg * HH * HH + hb;

    // ---- preload Wh slice -> BsW[n][kperm], once ----
    for (int i = tid; i < 256 * 32; i += 256) {    // float4 granules: 256k x 32
        int kr = i >> 5;
        int nc = (i & 31) * 4;
        float4 v = *(const float4*)(Wg + (size_t)(k0 + kr) * HH + nc);
        int colk = (kr & ~7) | ((kr & 3) << 1) | ((kr >> 2) & 1);
        BsW[(nc + 0) * 264 + colk] = f2tf32(v.x);
        BsW[(nc + 1) * 264 + colk] = f2tf32(v.y);
        BsW[(nc + 2) * 264 + colk] = f2tf32(v.z);
        BsW[(nc + 3) * 264 + colk] = f2tf32(v.w);
    }

    // Activation role: batch row b = blockIdx.x, cols tid*4..+3
    const int bown = blockIdx.x;
    const int hcol = tid * 4;
    float4 creg = make_float4(0.f, 0.f, 0.f, 0.f);
    float4 bb0 = *(const float4*)(bias + hcol);
    float4 bb1 = *(const float4*)(bias + 1024 + hcol);
    float4 bb2 = *(const float4*)(bias + 2048 + hcol);
    float4 bb3 = *(const float4*)(bias + 3072 + hcol);

    *(float4*)(g_h + bown * HH + hcol) = make_float4(0.f, 0.f, 0.f, 0.f);
    grid_barrier();

    // A stage: m = tid>>1, k-half (tid&1)*32, 8 float4
    const int am  = tid >> 1;
    const int ak0 = (tid & 1) * 32;
    const float* hrow = g_h + (size_t)am * HH + k0 + ak0;

    for (int t = 0; t < TT; t++) {
        float acc[4][4][4];
#pragma unroll
        for (int i = 0; i < 4; i++)
#pragma unroll
            for (int j = 0; j < 4; j++)
#pragma unroll
                for (int e = 0; e < 4; e++) acc[i][j][e] = 0.f;

        float4 st[8];
        // prologue: LDG chunk 0
#pragma unroll
        for (int j = 0; j < 8; j++) st[j] = *(const float4*)(hrow + 0 * 64 + j * 4);

#pragma unroll
        for (int c = 0; c < 4; c++) {
            uint32_t* buf = AsH + (c & 1) * (128 * 66);
            // STS staged chunk (cvt to tf32, permuted cols)
#pragma unroll
            for (int j = 0; j < 8; j++) {
                int kl = ak0 + j * 4;
                int cb = (kl & ~7) | ((kl >> 2) & 1);
                uint32_t* d = &buf[am * 66 + cb];
                d[0] = f2tf32(st[j].x); d[2] = f2tf32(st[j].y);
                d[4] = f2tf32(st[j].z); d[6] = f2tf32(st[j].w);
            }
            __syncthreads();
            // prefetch next chunk while mma runs
            if (c < 3) {
#pragma unroll
                for (int j = 0; j < 8; j++)
                    st[j] = *(const float4*)(hrow + (c + 1) * 64 + j * 4);
            }
            // mma burst: 8 k-steps of 8
#pragma unroll
            for (int kk = 0; kk < 8; kk++) {
                const int kca = kk * 8 + 2 * cq;            // col in AsH
                const int kcb = c * 64 + kk * 8 + 2 * cq;   // col in BsW
                uint32_t af[4][4], bf[4][2];
#pragma unroll
                for (int mt = 0; mt < 4; mt++) {
                    int m = m0w + mt * 16 + gq;
                    uint2 va = *(const uint2*)&buf[m * 66 + kca];
                    uint2 vb = *(const uint2*)&buf[(m + 8) * 66 + kca];
                    af[mt][0] = va.x; af[mt][1] = vb.x;
                    af[mt][2] = va.y; af[mt][3] = vb.y;
                }
#pragma unroll
                for (int nt2 = 0; nt2 < 4; nt2++) {
                    uint2 w = *(const uint2*)&BsW[(n0w + nt2 * 8 + gq) * 264 + kcb];
                    bf[nt2][0] = w.x; bf[nt2][1] = w.y;
                }
#pragma unroll
                for (int mt = 0; mt < 4; mt++)
#pragma unroll
                    for (int nt2 = 0; nt2 < 4; nt2++)
                        mma_tf32(acc[mt][nt2], af[mt], bf[nt2]);
            }
        }

        // store partials
        float* pbase = g_part + (size_t)ks * (BB * NGATE);
#pragma unroll
        for (int mt = 0; mt < 4; mt++) {
            int r0 = m0w + mt * 16 + gq;
#pragma unroll
            for (int nt2 = 0; nt2 < 4; nt2++) {
                int cc = n0 + n0w + nt2 * 8 + 2 * cq;
                *(float2*)(pbase + (size_t)r0 * NGATE + cc) =
                    make_float2(acc[mt][nt2][0], acc[mt][nt2][1]);
                *(float2*)(pbase + (size_t)(r0 + 8) * NGATE + cc) =
                    make_float2(acc[mt][nt2][2], acc[mt][nt2][3]);
            }
        }

        grid_barrier();   // partials visible

        // ---- fused activation ----
        {
            const float* xgb = xg + ((size_t)t * BB + bown) * NGATE;
            const float* p0 = g_part + (size_t)bown * NGATE;
            const float* p1 = p0 + 1 * (size_t)(BB * NGATE);
            const float* p2 = p0 + 2 * (size_t)(BB * NGATE);
            const float* p3 = p0 + 3 * (size_t)(BB * NGATE);

            float gv[4][4];
#pragma unroll
            for (int gi = 0; gi < 4; gi++) {
                int n = (gi << 10) | hcol;
                float4 v  = *(const float4*)(xgb + n);
                float4 q0 = *(const float4*)(p0 + n);
                float4 q1 = *(const float4*)(p1 + n);
                float4 q2 = *(const float4*)(p2 + n);
                float4 q3 = *(const float4*)(p3 + n);
                gv[gi][0] = v.x + q0.x + q1.x + q2.x + q3.x;
                gv[gi][1] = v.y + q0.y + q1.y + q2.y + q3.y;
                gv[gi][2] = v.z + q0.z + q1.z + q2.z + q3.z;
                gv[gi][3] = v.w + q0.w + q1.w + q2.w + q3.w;
            }
            gv[0][0] += bb0.x; gv[0][1] += bb0.y; gv[0][2] += bb0.z; gv[0][3] += bb0.w;
            gv[1][0] += bb1.x; gv[1][1] += bb1.y; gv[1][2] += bb1.z; gv[1][3] += bb1.w;
            gv[2][0] += bb2.x; gv[2][1] += bb2.y; gv[2][2] += bb2.z; gv[2][3] += bb2.w;
            gv[3][0] += bb3.x; gv[3][1] += bb3.y; gv[3][2] += bb3.z; gv[3][3] += bb3.w;

            float hv[4];
            float* cr = (float*)&creg;
#pragma unroll
            for (int e = 0; e < 4; e++) {
                float ig = 1.f / (1.f + expf(-gv[0][e]));
                float fg = 1.f / (1.f + expf(-gv[1][e]));
                float og = 1.f / (1.f + expf(-gv[2][e]));
                float ug = tanhf(gv[3][e]);
                float c = fg * cr[e] + ig * ug;
                cr[e] = c;
                hv[e] = og * tanhf(c);
            }
            float4 hvec = make_float4(hv[0], hv[1], hv[2], hv[3]);
            if (t == TT - 1)
                *(float4*)(out + bown * HH + hcol) = hvec;
            else
                *(float4*)(g_h + bown * HH + hcol) = hvec;
        }

        grid_barrier();   // h visible before next GEMM
    }
}

// ---------------------------------------------------------------------------
// Launch. Inputs: x[128,512,1024], adjacency (unused), Wx[4,1024,1024],
// Wh[4,1024,1024], b[4,1024]. Output: h [128,1024] f32. Graph: 2 nodes.
// ---------------------------------------------------------------------------
extern "C" void kernel_launch(void* const* d_in, const int* in_sizes, int n_in,
                              void* d_out, int out_size)
{
    const float* x    = (const float*)d_in[0];
    const float* Wx   = (const float*)d_in[2];
    const float* Wh   = (const float*)d_in[3];
    const float* bias = (const float*)d_in[4];
    float* out = (float*)d_out;

    float* xg;
    cudaGetSymbolAddress((void**)&xg, g_xg);

    const int rec_smem = (128 * 264 + 2 * 128 * 66) * 4;   // 202752 B
    static int configured = 0;
    if (!configured) {
        cudaFuncSetAttribute(lstm_recurrence,
                             cudaFuncAttributeMaxDynamicSharedMemorySize, rec_smem);
        configured = 1;
    }

    gemm_xgates<<<dim3(32, 512), 256>>>(x, Wx, xg);
    lstm_recurrence<<<NCTA, 256, rec_smem>>>(Wh, xg, bias, out);
}

// round 5
// speedup vs baseline: 1.0497x; 1.0497x over previous
#include <cuda_runtime.h>
#include <math.h>
#include <stdint.h>

#define BB 128
#define TT 512
#define DD 1024
#define HH 1024
#define NGATE 4096   // 4*H
#define NCTA 256     // persistent grid size (2/SM, all co-resident)

// Scratch (static device globals — no runtime allocation).
__device__ float g_xg[(size_t)TT * BB * NGATE];        // [t][b][4H] input projections
__device__ float g_part[4 * BB * NGATE];               // split-K partials [ks][b][4H]
__device__ float g_h[BB * HH];                         // recurrent h
__device__ unsigned g_bar;                             // grid barrier counter (never reset)

__device__ __forceinline__ uint32_t f2tf32(float f)
{
    uint32_t u;
    asm("cvt.rna.tf32.f32 %0, %1;" : "=r"(u) : "f"(f));
    return u;
}

__device__ __forceinline__ void mma_tf32(float* d, const uint32_t* a, const uint32_t* b)
{
    asm volatile(
        "mma.sync.aligned.m16n8k8.row.col.f32.tf32.tf32.f32 "
        "{%0,%1,%2,%3},{%4,%5,%6,%7},{%8,%9},{%0,%1,%2,%3};"
        : "+f"(d[0]), "+f"(d[1]), "+f"(d[2]), "+f"(d[3])
        : "r"(a[0]), "r"(a[1]), "r"(a[2]), "r"(a[3]), "r"(b[0]), "r"(b[1]));
}

// ---------------------------------------------------------------------------
// GEMM1 (tf32 tensor) — EXACT R3 version (measured best).
// xg[t][b][n] = sum_k x[b][t][k] * Wx[g][k][h]
// Block tile 128m x 128n x 32k. 8 warps 2x4; warp tile 64x32 (4x4 m16n8k8).
// ---------------------------------------------------------------------------
__global__ __launch_bounds__(256) void gemm_xgates(
    const float* __restrict__ x, const float* __restrict__ Wx,
    float* __restrict__ out)
{
    __shared__ uint32_t As[32 * 132];   // [k][m], tf32 bits
    __shared__ uint32_t Bs[32 * 132];   // [k][n], tf32 bits

    const int tid  = threadIdx.x;
    const int lane = tid & 31;
    const int wid  = tid >> 5;
    const int gq   = lane >> 2;
    const int cq   = lane & 3;

    const int t  = blockIdx.y;
    const int n0 = blockIdx.x * 128;
    const int gg = n0 >> 10;
    const int hb = n0 & 1023;

    const int m0w = (wid >> 2) * 64;
    const int n0w = (wid & 3) * 32;

    float acc[4][4][4];
#pragma unroll
    for (int i = 0; i < 4; i++)
#pragma unroll
        for (int j = 0; j < 4; j++)
#pragma unroll
            for (int e = 0; e < 4; e++) acc[i][j][e] = 0.f;

    const float* Wg = Wx + (size_t)gg * DD * HH + hb;

    const int am = tid >> 1;
    const int akq = (tid & 1) * 16;
    const int bk = tid >> 3;
    const int bnq = (tid & 7) * 16;

    for (int kt = 0; kt < DD; kt += 32) {
        {
            const float* src = x + (size_t)am * (TT * DD) + (size_t)t * DD + kt + akq;
#pragma unroll
            for (int j = 0; j < 4; j++) {
                float4 v = *(const float4*)(src + j * 4);
                As[(akq + j * 4 + 0) * 132 + am] = f2tf32(v.x);
                As[(akq + j * 4 + 1) * 132 + am] = f2tf32(v.y);
                As[(akq + j * 4 + 2) * 132 + am] = f2tf32(v.z);
                As[(akq + j * 4 + 3) * 132 + am] = f2tf32(v.w);
            }
        }
        {
            const float* src = Wg + (size_t)(kt + bk) * HH + bnq;
#pragma unroll
            for (int j = 0; j < 4; j++) {
                float4 v = *(const float4*)(src + j * 4);
                Bs[bk * 132 + bnq + j * 4 + 0] = f2tf32(v.x);
                Bs[bk * 132 + bnq + j * 4 + 1] = f2tf32(v.y);
                Bs[bk * 132 + bnq + j * 4 + 2] = f2tf32(v.z);
                Bs[bk * 132 + bnq + j * 4 + 3] = f2tf32(v.w);
            }
        }
        __syncthreads();

#pragma unroll
        for (int kk = 0; kk < 4; kk++) {
            const int kb = kk * 8;
            uint32_t af[4][4], bf[4][2];
#pragma unroll
            for (int mt = 0; mt < 4; mt++) {
                int m = m0w + mt * 16 + gq;
                af[mt][0] = As[(kb + cq) * 132 + m];
                af[mt][1] = As[(kb + cq) * 132 + m + 8];
                af[mt][2] = As[(kb + cq + 4) * 132 + m];
                af[mt][3] = As[(kb + cq + 4) * 132 + m + 8];
            }
#pragma unroll
            for (int nt = 0; nt < 4; nt++) {
                int n = n0w + nt * 8 + gq;
                bf[nt][0] = Bs[(kb + cq) * 132 + n];
                bf[nt][1] = Bs[(kb + cq + 4) * 132 + n];
            }
#pragma unroll
            for (int mt = 0; mt < 4; mt++)
#pragma unroll
                for (int nt = 0; nt < 4; nt++)
                    mma_tf32(acc[mt][nt], af[mt], bf[nt]);
        }
        __syncthreads();
    }

#pragma unroll
    for (int mt = 0; mt < 4; mt++) {
        int r0 = m0w + mt * 16 + gq;
#pragma unroll
        for (int nt = 0; nt < 4; nt++) {
            int cc = n0 + n0w + nt * 8 + 2 * cq;
            float* p0 = out + ((size_t)t * BB + r0) * NGATE + cc;
            float* p1 = out + ((size_t)t * BB + r0 + 8) * NGATE + cc;
            *(float2*)p0 = make_float2(acc[mt][nt][0], acc[mt][nt][1]);
            *(float2*)p1 = make_float2(acc[mt][nt][2], acc[mt][nt][3]);
        }
    }
}

// ---------------------------------------------------------------------------
// Grid barrier: stateless generation counter.
// ---------------------------------------------------------------------------
__device__ __forceinline__ void grid_barrier()
{
    __syncthreads();
    if (threadIdx.x == 0) {
        __threadfence();
        unsigned old = atomicAdd(&g_bar, 1u);
        unsigned target = (old / NCTA + 1u) * (unsigned)NCTA;
        while (atomicAdd(&g_bar, 0u) < target) { __nanosleep(32); }
        __threadfence();
    }
    __syncthreads();
}

// ---------------------------------------------------------------------------
// Persistent recurrence (tf32): 256 CTAs (2/SM) x 256 threads, 512 steps.
// CTA = (n-tile 0..63 width 64, k-split 0..3). Wh slice (256k x 64n, tf32)
// persists in smem (67.6 KB); h streams per step in 8 chunks of k32 (R3
// layout). Warp tile 32x32 (2x4 m16n8k8). Activation: CTA owns half of
// batch row (bx>>1), cols (bx&1)*512 + tid*2; c stays in registers.
// ---------------------------------------------------------------------------
extern __shared__ uint32_t dynsmem[];

__global__ __launch_bounds__(256, 2) void lstm_recurrence(
    const float* __restrict__ Wh, const float* __restrict__ xg,
    const float* __restrict__ bias, float* __restrict__ out)
{
    uint32_t* BsW = dynsmem;               // [256][66] persistent Wh tile (tf32), [k][n]
    uint32_t* AsH = dynsmem + 256 * 66;    // [32][132] streamed h tile (tf32), [k][m]

    const int tid  = threadIdx.x;
    const int lane = tid & 31;
    const int wid  = tid >> 5;
    const int gq   = lane >> 2;
    const int cq   = lane & 3;

    const int nt = blockIdx.x & 63;     // n-tile 0..63 (width 64)
    const int ks = blockIdx.x >> 6;     // k-split 0..3
    const int n0 = nt * 64;
    const int gg = n0 >> 10;
    const int hb = n0 & 1023;
    const int k0 = ks * 256;

    const int m0w = (wid >> 1) * 32;    // 4 warps along m
    const int n0w = (wid & 1) * 32;     // 2 warps along n

    const float* Wg = Wh + (size_t)gg * HH * HH + hb;

    // ---- preload Wh slice into smem (tf32), once ----
    for (int i = tid; i < 256 * 16; i += 256) {   // float4 granules: 256k x 16
        int kr = i >> 4;
        int nc = (i & 15) * 4;
        float4 v = *(const float4*)(Wg + (size_t)(k0 + kr) * HH + nc);
        BsW[kr * 66 + nc + 0] = f2tf32(v.x);
        BsW[kr * 66 + nc + 1] = f2tf32(v.y);
        BsW[kr * 66 + nc + 2] = f2tf32(v.z);
        BsW[kr * 66 + nc + 3] = f2tf32(v.w);
    }

    // Activation role: row bown = bx>>1, two cols hc2 = (bx&1)*512 + tid*2
    const int bown = blockIdx.x >> 1;
    const int hc2  = (blockIdx.x & 1) * 512 + tid * 2;
    float2 creg = make_float2(0.f, 0.f);
    float2 bb0 = *(const float2*)(bias + hc2);
    float2 bb1 = *(const float2*)(bias + 1024 + hc2);
    float2 bb2 = *(const float2*)(bias + 2048 + hc2);
    float2 bb3 = *(const float2*)(bias + 3072 + hc2);

    *(float2*)(g_h + bown * HH + hc2) = make_float2(0.f, 0.f);
    grid_barrier();

    const int am = tid >> 1;
    const int akq = (tid & 1) * 16;

    for (int t = 0; t < TT; t++) {
        float acc[2][4][4];
#pragma unroll
        for (int i = 0; i < 2; i++)
#pragma unroll
            for (int j = 0; j < 4; j++)
#pragma unroll
                for (int e = 0; e < 4; e++) acc[i][j][e] = 0.f;

        for (int kt = 0; kt < 8; kt++) {   // 8 chunks of k32
            const float* src = g_h + (size_t)am * HH + k0 + kt * 32 + akq;
#pragma unroll
            for (int j = 0; j < 4; j++) {
                float4 v = *(const float4*)(src + j * 4);
                AsH[(akq + j * 4 + 0) * 132 + am] = f2tf32(v.x);
                AsH[(akq + j * 4 + 1) * 132 + am] = f2tf32(v.y);
                AsH[(akq + j * 4 + 2) * 132 + am] = f2tf32(v.z);
                AsH[(akq + j * 4 + 3) * 132 + am] = f2tf32(v.w);
            }
            __syncthreads();

#pragma unroll
            for (int kk = 0; kk < 4; kk++) {
                const int kb = kk * 8;
                const int kw = kt * 32 + kb;
                uint32_t af[2][4], bf[4][2];
#pragma unroll
                for (int mt = 0; mt < 2; mt++) {
                    int m = m0w + mt * 16 + gq;
                    af[mt][0] = AsH[(kb + cq) * 132 + m];
                    af[mt][1] = AsH[(kb + cq) * 132 + m + 8];
                    af[mt][2] = AsH[(kb + cq + 4) * 132 + m];
                    af[mt][3] = AsH[(kb + cq + 4) * 132 + m + 8];
                }
#pragma unroll
                for (int nt2 = 0; nt2 < 4; nt2++) {
                    int n = n0w + nt2 * 8 + gq;
                    bf[nt2][0] = BsW[(kw + cq) * 66 + n];
                    bf[nt2][1] = BsW[(kw + cq + 4) * 66 + n];
                }
#pragma unroll
                for (int mt = 0; mt < 2; mt++)
#pragma unroll
                    for (int nt2 = 0; nt2 < 4; nt2++)
                        mma_tf32(acc[mt][nt2], af[mt], bf[nt2]);
            }
            __syncthreads();
        }

        // store partials
        float* pbase = g_part + (size_t)ks * (BB * NGATE);
#pragma unroll
        for (int mt = 0; mt < 2; mt++) {
            int r0 = m0w + mt * 16 + gq;
#pragma unroll
            for (int nt2 = 0; nt2 < 4; nt2++) {
                int cc = n0 + n0w + nt2 * 8 + 2 * cq;
                *(float2*)(pbase + (size_t)r0 * NGATE + cc) =
                    make_float2(acc[mt][nt2][0], acc[mt][nt2][1]);
                *(float2*)(pbase + (size_t)(r0 + 8) * NGATE + cc) =
                    make_float2(acc[mt][nt2][2], acc[mt][nt2][3]);
            }
        }

        grid_barrier();   // partials visible

        // ---- fused activation (half row per CTA) ----
        {
            const float* xgb = xg + ((size_t)t * BB + bown) * NGATE;
            const float* p0 = g_part + (size_t)bown * NGATE;
            const float* p1 = p0 + 1 * (size_t)(BB * NGATE);
            const float* p2 = p0 + 2 * (size_t)(BB * NGATE);
            const float* p3 = p0 + 3 * (size_t)(BB * NGATE);

            float gv[4][2];
#pragma unroll
            for (int gi = 0; gi < 4; gi++) {
                int n = (gi << 10) | hc2;
                float2 v  = *(const float2*)(xgb + n);
                float2 q0 = *(const float2*)(p0 + n);
                float2 q1 = *(const float2*)(p1 + n);
                float2 q2 = *(const float2*)(p2 + n);
                float2 q3 = *(const float2*)(p3 + n);
                gv[gi][0] = v.x + q0.x + q1.x + q2.x + q3.x;
                gv[gi][1] = v.y + q0.y + q1.y + q2.y + q3.y;
            }
            gv[0][0] += bb0.x; gv[0][1] += bb0.y;
            gv[1][0] += bb1.x; gv[1][1] += bb1.y;
            gv[2][0] += bb2.x; gv[2][1] += bb2.y;
            gv[3][0] += bb3.x; gv[3][1] += bb3.y;

            float hv[2];
            float* cr = (float*)&creg;
#pragma unroll
            for (int e = 0; e < 2; e++) {
                float ig = 1.f / (1.f + expf(-gv[0][e]));
                float fg = 1.f / (1.f + expf(-gv[1][e]));
                float og = 1.f / (1.f + expf(-gv[2][e]));
                float ug = tanhf(gv[3][e]);
                float c = fg * cr[e] + ig * ug;
                cr[e] = c;
                hv[e] = og * tanhf(c);
            }
            float2 hvec = make_float2(hv[0], hv[1]);
            if (t == TT - 1)
                *(float2*)(out + bown * HH + hc2) = hvec;
            else
                *(float2*)(g_h + bown * HH + hc2) = hvec;
        }

        grid_barrier();   // h visible before next GEMM
    }
}

// ---------------------------------------------------------------------------
// Launch. Inputs: x[128,512,1024], adjacency (unused), Wx[4,1024,1024],
// Wh[4,1024,1024], b[4,1024]. Output: h [128,1024] f32. Graph: 2 nodes.
// ---------------------------------------------------------------------------
extern "C" void kernel_launch(void* const* d_in, const int* in_sizes, int n_in,
                              void* d_out, int out_size)
{
    const float* x    = (const float*)d_in[0];
    const float* Wx   = (const float*)d_in[2];
    const float* Wh   = (const float*)d_in[3];
    const float* bias = (const float*)d_in[4];
    float* out = (float*)d_out;

    float* xg;
    cudaGetSymbolAddress((void**)&xg, g_xg);

    const int rec_smem = (256 * 66 + 32 * 132) * 4;   // 84480 B -> 2 CTAs/SM
    static int configured = 0;
    if (!configured) {
        cudaFuncSetAttribute(lstm_recurrence,
                             cudaFuncAttributeMaxDynamicSharedMemorySize, rec_smem);
        configured = 1;
    }

    gemm_xgates<<<dim3(32, 512), 256>>>(x, Wx, xg);
    lstm_recurrence<<<NCTA, 256, rec_smem>>>(Wh, xg, bias, out);
}

// round 6
// speedup vs baseline: 1.4214x; 1.3541x over previous
#include <cuda_runtime.h>
#include <math.h>
#include <stdint.h>

#define BB 128
#define TT 512
#define DD 1024
#define HH 1024
#define NGATE 4096   // 4*H
#define NCTA 128     // persistent grid size (1/SM, all co-resident)

// Scratch (static device globals — no runtime allocation).
__device__ float g_xg[(size_t)TT * BB * NGATE];        // [t][b][4H] input projections
__device__ float g_part[4 * BB * NGATE];               // split-K partials [ks][b][4H]
__device__ float g_h[BB * HH];                         // recurrent h
__device__ unsigned g_bar;                             // grid barrier counter (never reset)

__device__ __forceinline__ uint32_t f2tf32(float f)
{
    uint32_t u;
    asm("cvt.rna.tf32.f32 %0, %1;" : "=r"(u) : "f"(f));
    return u;
}

__device__ __forceinline__ void mma_tf32(float* d, const uint32_t* a, const uint32_t* b)
{
    asm volatile(
        "mma.sync.aligned.m16n8k8.row.col.f32.tf32.tf32.f32 "
        "{%0,%1,%2,%3},{%4,%5,%6,%7},{%8,%9},{%0,%1,%2,%3};"
        : "+f"(d[0]), "+f"(d[1]), "+f"(d[2]), "+f"(d[3])
        : "r"(a[0]), "r"(a[1]), "r"(a[2]), "r"(a[3]), "r"(b[0]), "r"(b[1]));
}

// ---------------------------------------------------------------------------
// GEMM1 (tf32 tensor) — EXACT R3 version (measured best).
// xg[t][b][n] = sum_k x[b][t][k] * Wx[g][k][h]
// Block tile 128m x 128n x 32k. 8 warps 2x4; warp tile 64x32 (4x4 m16n8k8).
// ---------------------------------------------------------------------------
__global__ __launch_bounds__(256) void gemm_xgates(
    const float* __restrict__ x, const float* __restrict__ Wx,
    float* __restrict__ out)
{
    __shared__ uint32_t As[32 * 132];   // [k][m], tf32 bits
    __shared__ uint32_t Bs[32 * 132];   // [k][n], tf32 bits

    const int tid  = threadIdx.x;
    const int lane = tid & 31;
    const int wid  = tid >> 5;
    const int gq   = lane >> 2;
    const int cq   = lane & 3;

    const int t  = blockIdx.y;
    const int n0 = blockIdx.x * 128;
    const int gg = n0 >> 10;
    const int hb = n0 & 1023;

    const int m0w = (wid >> 2) * 64;
    const int n0w = (wid & 3) * 32;

    float acc[4][4][4];
#pragma unroll
    for (int i = 0; i < 4; i++)
#pragma unroll
        for (int j = 0; j < 4; j++)
#pragma unroll
            for (int e = 0; e < 4; e++) acc[i][j][e] = 0.f;

    const float* Wg = Wx + (size_t)gg * DD * HH + hb;

    const int am = tid >> 1;
    const int akq = (tid & 1) * 16;
    const int bk = tid >> 3;
    const int bnq = (tid & 7) * 16;

    for (int kt = 0; kt < DD; kt += 32) {
        {
            const float* src = x + (size_t)am * (TT * DD) + (size_t)t * DD + kt + akq;
#pragma unroll
            for (int j = 0; j < 4; j++) {
                float4 v = *(const float4*)(src + j * 4);
                As[(akq + j * 4 + 0) * 132 + am] = f2tf32(v.x);
                As[(akq + j * 4 + 1) * 132 + am] = f2tf32(v.y);
                As[(akq + j * 4 + 2) * 132 + am] = f2tf32(v.z);
                As[(akq + j * 4 + 3) * 132 + am] = f2tf32(v.w);
            }
        }
        {
            const float* src = Wg + (size_t)(kt + bk) * HH + bnq;
#pragma unroll
            for (int j = 0; j < 4; j++) {
                float4 v = *(const float4*)(src + j * 4);
                Bs[bk * 132 + bnq + j * 4 + 0] = f2tf32(v.x);
                Bs[bk * 132 + bnq + j * 4 + 1] = f2tf32(v.y);
                Bs[bk * 132 + bnq + j * 4 + 2] = f2tf32(v.z);
                Bs[bk * 132 + bnq + j * 4 + 3] = f2tf32(v.w);
            }
        }
        __syncthreads();

#pragma unroll
        for (int kk = 0; kk < 4; kk++) {
            const int kb = kk * 8;
            uint32_t af[4][4], bf[4][2];
#pragma unroll
            for (int mt = 0; mt < 4; mt++) {
                int m = m0w + mt * 16 + gq;
                af[mt][0] = As[(kb + cq) * 132 + m];
                af[mt][1] = As[(kb + cq) * 132 + m + 8];
                af[mt][2] = As[(kb + cq + 4) * 132 + m];
                af[mt][3] = As[(kb + cq + 4) * 132 + m + 8];
            }
#pragma unroll
            for (int nt = 0; nt < 4; nt++) {
                int n = n0w + nt * 8 + gq;
                bf[nt][0] = Bs[(kb + cq) * 132 + n];
                bf[nt][1] = Bs[(kb + cq + 4) * 132 + n];
            }
#pragma unroll
            for (int mt = 0; mt < 4; mt++)
#pragma unroll
                for (int nt = 0; nt < 4; nt++)
                    mma_tf32(acc[mt][nt], af[mt], bf[nt]);
        }
        __syncthreads();
    }

#pragma unroll
    for (int mt = 0; mt < 4; mt++) {
        int r0 = m0w + mt * 16 + gq;
#pragma unroll
        for (int nt = 0; nt < 4; nt++) {
            int cc = n0 + n0w + nt * 8 + 2 * cq;
            float* p0 = out + ((size_t)t * BB + r0) * NGATE + cc;
            float* p1 = out + ((size_t)t * BB + r0 + 8) * NGATE + cc;
            *(float2*)p0 = make_float2(acc[mt][nt][0], acc[mt][nt][1]);
            *(float2*)p1 = make_float2(acc[mt][nt][2], acc[mt][nt][3]);
        }
    }
}

// ---------------------------------------------------------------------------
// Grid barrier: stateless generation counter.
// ---------------------------------------------------------------------------
__device__ __forceinline__ void grid_barrier()
{
    __syncthreads();
    if (threadIdx.x == 0) {
        __threadfence();
        unsigned old = atomicAdd(&g_bar, 1u);
        unsigned target = (old / NCTA + 1u) * (unsigned)NCTA;
        while (atomicAdd(&g_bar, 0u) < target) { __nanosleep(32); }
        __threadfence();
    }
    __syncthreads();
}

// ---------------------------------------------------------------------------
// Persistent recurrence (tf32): 128 CTAs x 256 threads, 512 steps.
// CTA = (n-tile 0..31 width 128, k-split 0..3). Wh slice (256k x 128n)
// persists in smem [k][n] stride 132. h streams per step in 8 chunks of k32
// through DOUBLE-BUFFERED AsH[2][32][132] (identical layout/writer to R3)
// with register-staged LDG prefetch of the next chunk issued before each mma
// burst. 8 syncthreads/step (was 16). Activation: CTA b owns row b, c in regs.
// ---------------------------------------------------------------------------
extern __shared__ uint32_t dynsmem[];

__global__ __launch_bounds__(256) void lstm_recurrence(
    const float* __restrict__ Wh, const float* __restrict__ xg,
    const float* __restrict__ bias, float* __restrict__ out)
{
    uint32_t* BsW = dynsmem;                  // [256][132] persistent Wh (tf32) [k][n]
    uint32_t* AsH = dynsmem + 256 * 132;      // [2][32][132] ping-pong h tile [k][m]

    const int tid  = threadIdx.x;
    const int lane = tid & 31;
    const int wid  = tid >> 5;
    const int gq   = lane >> 2;
    const int cq   = lane & 3;

    const int nt = blockIdx.x & 31;
    const int ks = blockIdx.x >> 5;
    const int n0 = nt * 128;
    const int gg = n0 >> 10;
    const int hb = n0 & 1023;
    const int k0 = ks * 256;

    const int m0w = (wid >> 2) * 64;
    const int n0w = (wid & 3) * 32;

    const float* Wg = Wh + (size_t)gg * HH * HH + hb;

    // ---- preload Wh slice -> BsW[k][n], once ----
    for (int i = tid; i < 256 * 32; i += 256) {   // float4 granules: 256k x 32
        int kr = i >> 5;
        int nc = (i & 31) * 4;
        float4 v = *(const float4*)(Wg + (size_t)(k0 + kr) * HH + nc);
        BsW[kr * 132 + nc + 0] = f2tf32(v.x);
        BsW[kr * 132 + nc + 1] = f2tf32(v.y);
        BsW[kr * 132 + nc + 2] = f2tf32(v.z);
        BsW[kr * 132 + nc + 3] = f2tf32(v.w);
    }

    // Activation role: batch row b = blockIdx.x, cols tid*4..+3
    const int bown = blockIdx.x;
    const int hcol = tid * 4;
    float4 creg = make_float4(0.f, 0.f, 0.f, 0.f);
    float4 bb0 = *(const float4*)(bias + hcol);
    float4 bb1 = *(const float4*)(bias + 1024 + hcol);
    float4 bb2 = *(const float4*)(bias + 2048 + hcol);
    float4 bb3 = *(const float4*)(bias + 3072 + hcol);

    *(float4*)(g_h + bown * HH + hcol) = make_float4(0.f, 0.f, 0.f, 0.f);
    grid_barrier();

    // A stage: m = tid>>1, k-half (tid&1)*16 within each k32 chunk
    const int am  = tid >> 1;
    const int akq = (tid & 1) * 16;
    const float* hrow = g_h + (size_t)am * HH + k0 + akq;

    for (int t = 0; t < TT; t++) {
        float acc[4][4][4];
#pragma unroll
        for (int i = 0; i < 4; i++)
#pragma unroll
            for (int j = 0; j < 4; j++)
#pragma unroll
                for (int e = 0; e < 4; e++) acc[i][j][e] = 0.f;

        float4 st[4];
        // prologue: LDG + STS chunk 0 into buffer 0
#pragma unroll
        for (int j = 0; j < 4; j++) st[j] = *(const float4*)(hrow + j * 4);
#pragma unroll
        for (int j = 0; j < 4; j++) {
            int kr = akq + j * 4;
            AsH[(kr + 0) * 132 + am] = f2tf32(st[j].x);
            AsH[(kr + 1) * 132 + am] = f2tf32(st[j].y);
            AsH[(kr + 2) * 132 + am] = f2tf32(st[j].z);
            AsH[(kr + 3) * 132 + am] = f2tf32(st[j].w);
        }
        __syncthreads();

#pragma unroll
        for (int kt = 0; kt < 8; kt++) {
            uint32_t* buf = AsH + (kt & 1) * (32 * 132);
            // prefetch next chunk from global (hidden behind mma burst)
            if (kt < 7) {
#pragma unroll
                for (int j = 0; j < 4; j++)
                    st[j] = *(const float4*)(hrow + (kt + 1) * 32 + j * 4);
            }
            // mma burst: 4 k-steps of 8
#pragma unroll
            for (int kk = 0; kk < 4; kk++) {
                const int kb = kk * 8;
                const int kw = kt * 32 + kb;
                uint32_t af[4][4], bf[4][2];
#pragma unroll
                for (int mt = 0; mt < 4; mt++) {
                    int m = m0w + mt * 16 + gq;
                    af[mt][0] = buf[(kb + cq) * 132 + m];
                    af[mt][1] = buf[(kb + cq) * 132 + m + 8];
                    af[mt][2] = buf[(kb + cq + 4) * 132 + m];
                    af[mt][3] = buf[(kb + cq + 4) * 132 + m + 8];
                }
#pragma unroll
                for (int nt2 = 0; nt2 < 4; nt2++) {
                    int n = n0w + nt2 * 8 + gq;
                    bf[nt2][0] = BsW[(kw + cq) * 132 + n];
                    bf[nt2][1] = BsW[(kw + cq + 4) * 132 + n];
                }
#pragma unroll
                for (int mt = 0; mt < 4; mt++)
#pragma unroll
                    for (int nt2 = 0; nt2 < 4; nt2++)
                        mma_tf32(acc[mt][nt2], af[mt], bf[nt2]);
            }
            // stage next chunk into the other buffer, one sync per chunk
            if (kt < 7) {
                uint32_t* nb = AsH + ((kt + 1) & 1) * (32 * 132);
#pragma unroll
                for (int j = 0; j < 4; j++) {
                    int kr = akq + j * 4;
                    nb[(kr + 0) * 132 + am] = f2tf32(st[j].x);
                    nb[(kr + 1) * 132 + am] = f2tf32(st[j].y);
                    nb[(kr + 2) * 132 + am] = f2tf32(st[j].z);
                    nb[(kr + 3) * 132 + am] = f2tf32(st[j].w);
                }
                __syncthreads();
            }
        }

        // store partials
        float* pbase = g_part + (size_t)ks * (BB * NGATE);
#pragma unroll
        for (int mt = 0; mt < 4; mt++) {
            int r0 = m0w + mt * 16 + gq;
#pragma unroll
            for (int nt2 = 0; nt2 < 4; nt2++) {
                int cc = n0 + n0w + nt2 * 8 + 2 * cq;
                *(float2*)(pbase + (size_t)r0 * NGATE + cc) =
                    make_float2(acc[mt][nt2][0], acc[mt][nt2][1]);
                *(float2*)(pbase + (size_t)(r0 + 8) * NGATE + cc) =
                    make_float2(acc[mt][nt2][2], acc[mt][nt2][3]);
            }
        }

        grid_barrier();   // partials visible

        // ---- fused activation ----
        {
            const float* xgb = xg + ((size_t)t * BB + bown) * NGATE;
            const float* p0 = g_part + (size_t)bown * NGATE;
            const float* p1 = p0 + 1 * (size_t)(BB * NGATE);
            const float* p2 = p0 + 2 * (size_t)(BB * NGATE);
            const float* p3 = p0 + 3 * (size_t)(BB * NGATE);

            float gv[4][4];
#pragma unroll
            for (int gi = 0; gi < 4; gi++) {
                int n = (gi << 10) | hcol;
                float4 v  = *(const float4*)(xgb + n);
                float4 q0 = *(const float4*)(p0 + n);
                float4 q1 = *(const float4*)(p1 + n);
                float4 q2 = *(const float4*)(p2 + n);
                float4 q3 = *(const float4*)(p3 + n);
                gv[gi][0] = v.x + q0.x + q1.x + q2.x + q3.x;
                gv[gi][1] = v.y + q0.y + q1.y + q2.y + q3.y;
                gv[gi][2] = v.z + q0.z + q1.z + q2.z + q3.z;
                gv[gi][3] = v.w + q0.w + q1.w + q2.w + q3.w;
            }
            gv[0][0] += bb0.x; gv[0][1] += bb0.y; gv[0][2] += bb0.z; gv[0][3] += bb0.w;
            gv[1][0] += bb1.x; gv[1][1] += bb1.y; gv[1][2] += bb1.z; gv[1][3] += bb1.w;
            gv[2][0] += bb2.x; gv[2][1] += bb2.y; gv[2][2] += bb2.z; gv[2][3] += bb2.w;
            gv[3][0] += bb3.x; gv[3][1] += bb3.y; gv[3][2] += bb3.z; gv[3][3] += bb3.w;

            float hv[4];
            float* cr = (float*)&creg;
#pragma unroll
            for (int e = 0; e < 4; e++) {
                float ig = 1.f / (1.f + expf(-gv[0][e]));
                float fg = 1.f / (1.f + expf(-gv[1][e]));
                float og = 1.f / (1.f + expf(-gv[2][e]));
                float ug = tanhf(gv[3][e]);
                float c = fg * cr[e] + ig * ug;
                cr[e] = c;
                hv[e] = og * tanhf(c);
            }
            float4 hvec = make_float4(hv[0], hv[1], hv[2], hv[3]);
            if (t == TT - 1)
                *(float4*)(out + bown * HH + hcol) = hvec;
            else
                *(float4*)(g_h + bown * HH + hcol) = hvec;
        }

        grid_barrier();   // h visible before next GEMM
    }
}

// ---------------------------------------------------------------------------
// Launch. Inputs: x[128,512,1024], adjacency (unused), Wx[4,1024,1024],
// Wh[4,1024,1024], b[4,1024]. Output: h [128,1024] f32. Graph: 2 nodes.
// ---------------------------------------------------------------------------
extern "C" void kernel_launch(void* const* d_in, const int* in_sizes, int n_in,
                              void* d_out, int out_size)
{
    const float* x    = (const float*)d_in[0];
    const float* Wx   = (const float*)d_in[2];
    const float* Wh   = (const float*)d_in[3];
    const float* bias = (const float*)d_in[4];
    float* out = (float*)d_out;

    float* xg;
    cudaGetSymbolAddress((void**)&xg, g_xg);

    const int rec_smem = (256 * 132 + 2 * 32 * 132) * 4;   // 168960 B, 1 CTA/SM
    static int configured = 0;
    if (!configured) {
        cudaFuncSetAttribute(lstm_recurrence,
                             cudaFuncAttributeMaxDynamicSharedMemorySize, rec_smem);
        configured = 1;
    }

    gemm_xgates<<<dim3(32, 512), 256>>>(x, Wx, xg);
    lstm_recurrence<<<NCTA, 256, rec_smem>>>(Wh, xg, bias, out);
}

// round 7
// speedup vs baseline: 1.6414x; 1.1547x over previous
#include <cuda_runtime.h>
#include <math.h>
#include <stdint.h>

#define BB 128
#define TT 512
#define DD 1024
#define HH 1024
#define NGATE 4096   // 4*H
#define NCTA 128     // persistent grid size (1/SM, all co-resident)

#define LDA 136      // smem row stride (words): 136 % 32 == 8 -> conflict-free fragment reads

// Scratch (static device globals — no runtime allocation).
__device__ float g_xg[(size_t)TT * BB * NGATE];        // [t][b][4H] input projections
__device__ float g_part[4 * BB * NGATE];               // split-K partials [ks][b][4H]
__device__ float g_h[BB * HH];                         // recurrent h
__device__ unsigned g_bar;                             // grid barrier counter (never reset)

__device__ __forceinline__ uint32_t f2tf32(float f)
{
    uint32_t u;
    asm("cvt.rna.tf32.f32 %0, %1;" : "=r"(u) : "f"(f));
    return u;
}

__device__ __forceinline__ void mma_tf32(float* d, const uint32_t* a, const uint32_t* b)
{
    asm volatile(
        "mma.sync.aligned.m16n8k8.row.col.f32.tf32.tf32.f32 "
        "{%0,%1,%2,%3},{%4,%5,%6,%7},{%8,%9},{%0,%1,%2,%3};"
        : "+f"(d[0]), "+f"(d[1]), "+f"(d[2]), "+f"(d[3])
        : "r"(a[0]), "r"(a[1]), "r"(a[2]), "r"(a[3]), "r"(b[0]), "r"(b[1]));
}

// ---------------------------------------------------------------------------
// GEMM1 (tf32 tensor): xg[t][b][n] = sum_k x[b][t][k] * Wx[g][k][h]
// R3 structure; smem stride 132 -> 136 (conflict-free fragment reads).
// ---------------------------------------------------------------------------
__global__ __launch_bounds__(256) void gemm_xgates(
    const float* __restrict__ x, const float* __restrict__ Wx,
    float* __restrict__ out)
{
    __shared__ uint32_t As[32 * LDA];   // [k][m], tf32 bits
    __shared__ uint32_t Bs[32 * LDA];   // [k][n], tf32 bits

    const int tid  = threadIdx.x;
    const int lane = tid & 31;
    const int wid  = tid >> 5;
    const int gq   = lane >> 2;
    const int cq   = lane & 3;

    const int t  = blockIdx.y;
    const int n0 = blockIdx.x * 128;
    const int gg = n0 >> 10;
    const int hb = n0 & 1023;

    const int m0w = (wid >> 2) * 64;
    const int n0w = (wid & 3) * 32;

    float acc[4][4][4];
#pragma unroll
    for (int i = 0; i < 4; i++)
#pragma unroll
        for (int j = 0; j < 4; j++)
#pragma unroll
            for (int e = 0; e < 4; e++) acc[i][j][e] = 0.f;

    const float* Wg = Wx + (size_t)gg * DD * HH + hb;

    const int am = tid >> 1;
    const int akq = (tid & 1) * 16;
    const int bk = tid >> 3;
    const int bnq = (tid & 7) * 16;

    for (int kt = 0; kt < DD; kt += 32) {
        {
            const float* src = x + (size_t)am * (TT * DD) + (size_t)t * DD + kt + akq;
#pragma unroll
            for (int j = 0; j < 4; j++) {
                float4 v = *(const float4*)(src + j * 4);
                As[(akq + j * 4 + 0) * LDA + am] = f2tf32(v.x);
                As[(akq + j * 4 + 1) * LDA + am] = f2tf32(v.y);
                As[(akq + j * 4 + 2) * LDA + am] = f2tf32(v.z);
                As[(akq + j * 4 + 3) * LDA + am] = f2tf32(v.w);
            }
        }
        {
            const float* src = Wg + (size_t)(kt + bk) * HH + bnq;
#pragma unroll
            for (int j = 0; j < 4; j++) {
                float4 v = *(const float4*)(src + j * 4);
                Bs[bk * LDA + bnq + j * 4 + 0] = f2tf32(v.x);
                Bs[bk * LDA + bnq + j * 4 + 1] = f2tf32(v.y);
                Bs[bk * LDA + bnq + j * 4 + 2] = f2tf32(v.z);
                Bs[bk * LDA + bnq + j * 4 + 3] = f2tf32(v.w);
            }
        }
        __syncthreads();

#pragma unroll
        for (int kk = 0; kk < 4; kk++) {
            const int kb = kk * 8;
            uint32_t af[4][4], bf[4][2];
#pragma unroll
            for (int mt = 0; mt < 4; mt++) {
                int m = m0w + mt * 16 + gq;
                af[mt][0] = As[(kb + cq) * LDA + m];
                af[mt][1] = As[(kb + cq) * LDA + m + 8];
                af[mt][2] = As[(kb + cq + 4) * LDA + m];
                af[mt][3] = As[(kb + cq + 4) * LDA + m + 8];
            }
#pragma unroll
            for (int nt = 0; nt < 4; nt++) {
                int n = n0w + nt * 8 + gq;
                bf[nt][0] = Bs[(kb + cq) * LDA + n];
                bf[nt][1] = Bs[(kb + cq + 4) * LDA + n];
            }
#pragma unroll
            for (int mt = 0; mt < 4; mt++)
#pragma unroll
                for (int nt = 0; nt < 4; nt++)
                    mma_tf32(acc[mt][nt], af[mt], bf[nt]);
        }
        __syncthreads();
    }

#pragma unroll
    for (int mt = 0; mt < 4; mt++) {
        int r0 = m0w + mt * 16 + gq;
#pragma unroll
        for (int nt = 0; nt < 4; nt++) {
            int cc = n0 + n0w + nt * 8 + 2 * cq;
            float* p0 = out + ((size_t)t * BB + r0) * NGATE + cc;
            float* p1 = out + ((size_t)t * BB + r0 + 8) * NGATE + cc;
            *(float2*)p0 = make_float2(acc[mt][nt][0], acc[mt][nt][1]);
            *(float2*)p1 = make_float2(acc[mt][nt][2], acc[mt][nt][3]);
        }
    }
}

// ---------------------------------------------------------------------------
// Grid barrier: stateless generation counter.
// ---------------------------------------------------------------------------
__device__ __forceinline__ void grid_barrier()
{
    __syncthreads();
    if (threadIdx.x == 0) {
        __threadfence();
        unsigned old = atomicAdd(&g_bar, 1u);
        unsigned target = (old / NCTA + 1u) * (unsigned)NCTA;
        while (atomicAdd(&g_bar, 0u) < target) { __nanosleep(32); }
        __threadfence();
    }
    __syncthreads();
}

// ---------------------------------------------------------------------------
// Persistent recurrence (tf32): 128 CTAs x 256 threads, 512 steps.
// R6 structure (double-buffered AsH + LDG prefetch); stride 132 -> 136.
// ---------------------------------------------------------------------------
extern __shared__ uint32_t dynsmem[];

__global__ __launch_bounds__(256) void lstm_recurrence(
    const float* __restrict__ Wh, const float* __restrict__ xg,
    const float* __restrict__ bias, float* __restrict__ out)
{
    uint32_t* BsW = dynsmem;                  // [256][LDA] persistent Wh (tf32) [k][n]
    uint32_t* AsH = dynsmem + 256 * LDA;      // [2][32][LDA] ping-pong h tile [k][m]

    const int tid  = threadIdx.x;
    const int lane = tid & 31;
    const int wid  = tid >> 5;
    const int gq   = lane >> 2;
    const int cq   = lane & 3;

    const int nt = blockIdx.x & 31;
    const int ks = blockIdx.x >> 5;
    const int n0 = nt * 128;
    const int gg = n0 >> 10;
    const int hb = n0 & 1023;
    const int k0 = ks * 256;

    const int m0w = (wid >> 2) * 64;
    const int n0w = (wid & 3) * 32;

    const float* Wg = Wh + (size_t)gg * HH * HH + hb;

    // ---- preload Wh slice -> BsW[k][n], once (conflict-free STS.128) ----
    for (int i = tid; i < 256 * 32; i += 256) {   // float4 granules: 256k x 32
        int kr = i >> 5;
        int nc = (i & 31) * 4;
        float4 v = *(const float4*)(Wg + (size_t)(k0 + kr) * HH + nc);
        BsW[kr * LDA + nc + 0] = f2tf32(v.x);
        BsW[kr * LDA + nc + 1] = f2tf32(v.y);
        BsW[kr * LDA + nc + 2] = f2tf32(v.z);
        BsW[kr * LDA + nc + 3] = f2tf32(v.w);
    }

    // Activation role: batch row b = blockIdx.x, cols tid*4..+3
    const int bown = blockIdx.x;
    const int hcol = tid * 4;
    float4 creg = make_float4(0.f, 0.f, 0.f, 0.f);
    float4 bb0 = *(const float4*)(bias + hcol);
    float4 bb1 = *(const float4*)(bias + 1024 + hcol);
    float4 bb2 = *(const float4*)(bias + 2048 + hcol);
    float4 bb3 = *(const float4*)(bias + 3072 + hcol);

    *(float4*)(g_h + bown * HH + hcol) = make_float4(0.f, 0.f, 0.f, 0.f);
    grid_barrier();

    // A stage: m = tid>>1, k-half (tid&1)*16 within each k32 chunk
    const int am  = tid >> 1;
    const int akq = (tid & 1) * 16;
    const float* hrow = g_h + (size_t)am * HH + k0 + akq;

    for (int t = 0; t < TT; t++) {
        float acc[4][4][4];
#pragma unroll
        for (int i = 0; i < 4; i++)
#pragma unroll
            for (int j = 0; j < 4; j++)
#pragma unroll
                for (int e = 0; e < 4; e++) acc[i][j][e] = 0.f;

        float4 st[4];
        // prologue: LDG + STS chunk 0 into buffer 0
#pragma unroll
        for (int j = 0; j < 4; j++) st[j] = *(const float4*)(hrow + j * 4);
#pragma unroll
        for (int j = 0; j < 4; j++) {
            int kr = akq + j * 4;
            AsH[(kr + 0) * LDA + am] = f2tf32(st[j].x);
            AsH[(kr + 1) * LDA + am] = f2tf32(st[j].y);
            AsH[(kr + 2) * LDA + am] = f2tf32(st[j].z);
            AsH[(kr + 3) * LDA + am] = f2tf32(st[j].w);
        }
        __syncthreads();

#pragma unroll
        for (int kt = 0; kt < 8; kt++) {
            uint32_t* buf = AsH + (kt & 1) * (32 * LDA);
            // prefetch next chunk from global (hidden behind mma burst)
            if (kt < 7) {
#pragma unroll
                for (int j = 0; j < 4; j++)
                    st[j] = *(const float4*)(hrow + (kt + 1) * 32 + j * 4);
            }
            // mma burst: 4 k-steps of 8
#pragma unroll
            for (int kk = 0; kk < 4; kk++) {
                const int kb = kk * 8;
                const int kw = kt * 32 + kb;
                uint32_t af[4][4], bf[4][2];
#pragma unroll
                for (int mt = 0; mt < 4; mt++) {
                    int m = m0w + mt * 16 + gq;
                    af[mt][0] = buf[(kb + cq) * LDA + m];
                    af[mt][1] = buf[(kb + cq) * LDA + m + 8];
                    af[mt][2] = buf[(kb + cq + 4) * LDA + m];
                    af[mt][3] = buf[(kb + cq + 4) * LDA + m + 8];
                }
#pragma unroll
                for (int nt2 = 0; nt2 < 4; nt2++) {
                    int n = n0w + nt2 * 8 + gq;
                    bf[nt2][0] = BsW[(kw + cq) * LDA + n];
                    bf[nt2][1] = BsW[(kw + cq + 4) * LDA + n];
                }
#pragma unroll
                for (int mt = 0; mt < 4; mt++)
#pragma unroll
                    for (int nt2 = 0; nt2 < 4; nt2++)
                        mma_tf32(acc[mt][nt2], af[mt], bf[nt2]);
            }
            // stage next chunk into the other buffer, one sync per chunk
            if (kt < 7) {
                uint32_t* nb = AsH + ((kt + 1) & 1) * (32 * LDA);
#pragma unroll
                for (int j = 0; j < 4; j++) {
                    int kr = akq + j * 4;
                    nb[(kr + 0) * LDA + am] = f2tf32(st[j].x);
                    nb[(kr + 1) * LDA + am] = f2tf32(st[j].y);
                    nb[(kr + 2) * LDA + am] = f2tf32(st[j].z);
                    nb[(kr + 3) * LDA + am] = f2tf32(st[j].w);
                }
                __syncthreads();
            }
        }

        // store partials
        float* pbase = g_part + (size_t)ks * (BB * NGATE);
#pragma unroll
        for (int mt = 0; mt < 4; mt++) {
            int r0 = m0w + mt * 16 + gq;
#pragma unroll
            for (int nt2 = 0; nt2 < 4; nt2++) {
                int cc = n0 + n0w + nt2 * 8 + 2 * cq;
                *(float2*)(pbase + (size_t)r0 * NGATE + cc) =
                    make_float2(acc[mt][nt2][0], acc[mt][nt2][1]);
                *(float2*)(pbase + (size_t)(r0 + 8) * NGATE + cc) =
                    make_float2(acc[mt][nt2][2], acc[mt][nt2][3]);
            }
        }

        grid_barrier();   // partials visible

        // ---- fused activation ----
        {
            const float* xgb = xg + ((size_t)t * BB + bown) * NGATE;
            const float* p0 = g_part + (size_t)bown * NGATE;
            const float* p1 = p0 + 1 * (size_t)(BB * NGATE);
            const float* p2 = p0 + 2 * (size_t)(BB * NGATE);
            const float* p3 = p0 + 3 * (size_t)(BB * NGATE);

            float gv[4][4];
#pragma unroll
            for (int gi = 0; gi < 4; gi++) {
                int n = (gi << 10) | hcol;
                float4 v  = *(const float4*)(xgb + n);
                float4 q0 = *(const float4*)(p0 + n);
                float4 q1 = *(const float4*)(p1 + n);
                float4 q2 = *(const float4*)(p2 + n);
                float4 q3 = *(const float4*)(p3 + n);
                gv[gi][0] = v.x + q0.x + q1.x + q2.x + q3.x;
                gv[gi][1] = v.y + q0.y + q1.y + q2.y + q3.y;
                gv[gi][2] = v.z + q0.z + q1.z + q2.z + q3.z;
                gv[gi][3] = v.w + q0.w + q1.w + q2.w + q3.w;
            }
            gv[0][0] += bb0.x; gv[0][1] += bb0.y; gv[0][2] += bb0.z; gv[0][3] += bb0.w;
            gv[1][0] += bb1.x; gv[1][1] += bb1.y; gv[1][2] += bb1.z; gv[1][3] += bb1.w;
            gv[2][0] += bb2.x; gv[2][1] += bb2.y; gv[2][2] += bb2.z; gv[2][3] += bb2.w;
            gv[3][0] += bb3.x; gv[3][1] += bb3.y; gv[3][2] += bb3.z; gv[3][3] += bb3.w;

            float hv[4];
            float* cr = (float*)&creg;
#pragma unroll
            for (int e = 0; e < 4; e++) {
                float ig = 1.f / (1.f + expf(-gv[0][e]));
                float fg = 1.f / (1.f + expf(-gv[1][e]));
                float og = 1.f / (1.f + expf(-gv[2][e]));
                float ug = tanhf(gv[3][e]);
                float c = fg * cr[e] + ig * ug;
                cr[e] = c;
                hv[e] = og * tanhf(c);
            }
            float4 hvec = make_float4(hv[0], hv[1], hv[2], hv[3]);
            if (t == TT - 1)
                *(float4*)(out + bown * HH + hcol) = hvec;
            else
                *(float4*)(g_h + bown * HH + hcol) = hvec;
        }

        grid_barrier();   // h visible before next GEMM
    }
}

// ---------------------------------------------------------------------------
// Launch. Inputs: x[128,512,1024], adjacency (unused), Wx[4,1024,1024],
// Wh[4,1024,1024], b[4,1024]. Output: h [128,1024] f32. Graph: 2 nodes.
// ---------------------------------------------------------------------------
extern "C" void kernel_launch(void* const* d_in, const int* in_sizes, int n_in,
                              void* d_out, int out_size)
{
    const float* x    = (const float*)d_in[0];
    const float* Wx   = (const float*)d_in[2];
    const float* Wh   = (const float*)d_in[3];
    const float* bias = (const float*)d_in[4];
    float* out = (float*)d_out;

    float* xg;
    cudaGetSymbolAddress((void**)&xg, g_xg);

    const int rec_smem = (256 * LDA + 2 * 32 * LDA) * 4;   // 174080 B, 1 CTA/SM
    static int configured = 0;
    if (!configured) {
        cudaFuncSetAttribute(lstm_recurrence,
                             cudaFuncAttributeMaxDynamicSharedMemorySize, rec_smem);
        configured = 1;
    }

    gemm_xgates<<<dim3(32, 512), 256>>>(x, Wx, xg);
    lstm_recurrence<<<NCTA, 256, rec_smem>>>(Wh, xg, bias, out);
}